// round 3
// baseline (speedup 1.0000x reference)
#include <cuda_runtime.h>

// SegmentPhysicsModel — 3 sign-selected single-diode solves per sample.
//
// R3 changes vs R2 (6.6us):
//  * Staging loads widened: 11x LDG.32 -> 3x LDG.128 per thread (block tile of
//    256 samples x 11 feats = 704 float4s). Cuts L1tex wavefronts ~4x and the
//    LSU issue floor; the kernel is DRAM-latency exposed, not BW bound.
//  * NITER 5 -> 3. Fixed-point contraction factor <= ~3e-4/step on initial
//    relative error ~1e-2: converged below f32 eps in 2 steps; 3rd is margin.
//  * Full-block fast path (n % 256 == 0 here): no per-element guards.

#define TPB        256
#define NFEAT      11
#define TILE_F4    ((TPB * NFEAT) / 4)   // 704

#define JSC        170.0
#define ALPHA_ISC  0.0006f
#define T_REFC     298.15f
#define RS         0.01f
#define INV_RSH    0.002f              // 1/500
#define INV_GREF   (1.0f/1366.0f)
#define SOLAR_C    1366.0f
#define SUN_DIST   149600000.0f
#define NKB        (2.5f * 8.617333262e-05f)
#define LOG2E      1.4426950408889634

#define VT_REF_D   (2.5 * 8.617333262e-05 * 298.15)
// ex2 argument for 1/expm1(Voc/vt_ref): exp(x)-1 == exp(x) in f32 for x~36.6
#define INV_EM1_ARG ((float)(-(2.35 / VT_REF_D) * LOG2E))

#define C_A1       ((float)(JSC * 0.0604 * 0.0398))   // JSC * area_large
#define C_A2       ((float)(JSC * 0.0403 * 0.0306))   // JSC * area_small

#define STEP       0.99984f            // ~ -1/f'
#define NITER      3

__device__ __forceinline__ float ex2f(float z) {
    float r;
    asm("ex2.approx.f32 %0, %1;" : "=f"(r) : "f"(z));
    return r;
}

// One fixed-point step: I += STEP * (c0 - i0*e^z - u/Rsh - I),  z = u*k
__device__ __forceinline__ void fp_step(float& I, float v_cell, float c0,
                                        float i0, float k) {
    float u = fmaf(I, RS, v_cell);
    float e = ex2f(u * k);
    float t = fmaf(-i0, e, c0);
    t = fmaf(-INV_RSH, u, t);
    float f = t - I;
    I = fmaf(STEP, f, I);
}

__global__ void __launch_bounds__(TPB)
segment_physics_kernel(const float* __restrict__ x,
                       const float* __restrict__ f_xn,
                       const float* __restrict__ f_yn,
                       const float* __restrict__ f_xp,
                       const float* __restrict__ f_yp,
                       float* __restrict__ out, int n) {
    __shared__ float s[TPB * NFEAT];

    int i = blockIdx.x * TPB + threadIdx.x;
    bool full = (blockIdx.x + 1) * TPB <= n;   // all-256-samples block?

    if (full) {
        // Vectorized stage: 704 float4s per block, 3 per thread (last partial).
        const float4* xv = reinterpret_cast<const float4*>(x) +
                           (size_t)blockIdx.x * TILE_F4;
        float4* sv = reinterpret_cast<float4*>(s);
        #pragma unroll
        for (int k = 0; k < 3; ++k) {
            int idx = k * TPB + threadIdx.x;
            if (idx < TILE_F4) sv[idx] = xv[idx];
        }
    } else {
        int base = blockIdx.x * TPB * NFEAT;
        int total = n * NFEAT;
        #pragma unroll
        for (int j = 0; j < NFEAT; ++j) {
            int idx = j * TPB + threadIdx.x;
            int g = base + idx;
            if (g < total) s[idx] = x[g];
        }
    }
    __syncthreads();

    if (i >= n) return;

    const float* p = s + threadIdx.x * NFEAT;
    float sx   = p[0];
    float sy   = p[1];
    float tpx  = p[2];
    float tnx  = p[3];
    float tpy  = p[4];
    float tny  = p[5];
    float V    = p[6];
    float dist = p[7];

    float r   = SUN_DIST / dist;
    float irr = SOLAR_C * r * r;

    // Dark-side panel's root is negative -> clamps to 0; keep only lit side.
    bool  xp = sx > 0.0f;
    float Gx = irr * fabsf(sx);
    float Tx = xp ? tpx : tnx;
    float fx = xp ? f_xp[0] : f_xn[0];

    bool  yp = sy > 0.0f;
    float Gy = irr * fabsf(sy);
    float Ty = yp ? tpy : tny;
    float fy = yp ? f_yp[0] : f_yn[0];
    float cAY  = yp ? C_A2 : C_A1;     // y_pos: small cells, y_neg: large cells
    float parY = yp ? 10.0f : 6.0f;    // 180/18 vs 108/18

    float v_cell  = V * (1.0f / 18.0f);
    float inv_em1 = ex2f(INV_EM1_ARG);

    float gtx = (Gx * INV_GREF) * fmaf(ALPHA_ISC, Tx - T_REFC, 1.0f);
    float gty = (Gy * INV_GREF) * fmaf(ALPHA_ISC, Ty - T_REFC, 1.0f);

    float kx = (float)LOG2E / (NKB * Tx);
    float ky = (float)LOG2E / (NKB * Ty);

    float iph1 = C_A1 * gtx;           // X large cells  (parallel = 2)
    float iph2 = C_A2 * gtx;           // X small cells  (parallel = 7)
    float iph3 = cAY  * gty;           // Y selected config

    float i0_1 = C_A1 * inv_em1;
    float i0_2 = C_A2 * inv_em1;
    float i0_3 = cAY  * inv_em1;

    float c0_1 = iph1 + i0_1;
    float c0_2 = iph2 + i0_2;
    float c0_3 = iph3 + i0_3;

    float I1 = iph1, I2 = iph2, I3 = iph3;

    #pragma unroll
    for (int it = 0; it < NITER; ++it) {
        fp_step(I1, v_cell, c0_1, i0_1, kx);
        fp_step(I2, v_cell, c0_2, i0_2, kx);
        fp_step(I3, v_cell, c0_3, i0_3, ky);
    }

    float ix = fx * fmaf(2.0f, fmaxf(I1, 0.0f), 7.0f * fmaxf(I2, 0.0f));
    float iy = fy * parY * fmaxf(I3, 0.0f);
    out[i] = 0.92f * (ix + iy);
}

extern "C" void kernel_launch(void* const* d_in, const int* in_sizes, int n_in,
                              void* d_out, int out_size) {
    const float* x    = (const float*)d_in[0];
    const float* f_xn = (const float*)d_in[1];
    const float* f_yn = (const float*)d_in[2];
    const float* f_xp = (const float*)d_in[3];
    const float* f_yp = (const float*)d_in[4];
    float* out = (float*)d_out;

    int n = in_sizes[0] / NFEAT;
    int blocks = (n + TPB - 1) / TPB;
    segment_physics_kernel<<<blocks, TPB>>>(x, f_xn, f_yn, f_xp, f_yp, out, n);
}

// round 4
// speedup vs baseline: 1.0386x; 1.0386x over previous
#include <cuda_runtime.h>

// SegmentPhysicsModel — 3 sign-selected single-diode solves per sample.
//
// R4 changes vs R3 (ncu 6.18us, neutral vs R2 — kernel is latency/structure
// bound, not instruction bound):
//  * Warp-autonomous staging: warp w loads ITS OWN 32 samples (1408B = 88
//    aligned float4s) and syncs with __syncwarp only. Deletes the block
//    barrier, removing the max-over-8-warps DRAM latency from every CTA's
//    critical path.
//  * Factor scalars (f_xn..f_yp) loaded at kernel entry so they overlap the
//    x loads instead of trailing the compute.
//  * NITER=3 fixed-point steps (converged to f32 in 2; 3rd is margin),
//    division-free, ex2.approx with prefolded log2e.

#define TPB        256
#define NFEAT      11
#define WARP_F4    88                  // 32 samples * 11 floats / 4

#define JSC        170.0
#define ALPHA_ISC  0.0006f
#define T_REFC     298.15f
#define RS         0.01f
#define INV_RSH    0.002f
#define INV_GREF   (1.0f/1366.0f)
#define SOLAR_C    1366.0f
#define SUN_DIST   149600000.0f
#define NKB        (2.5f * 8.617333262e-05f)
#define LOG2E      1.4426950408889634

#define VT_REF_D   (2.5 * 8.617333262e-05 * 298.15)
#define INV_EM1_ARG ((float)(-(2.35 / VT_REF_D) * LOG2E))

#define C_A1       ((float)(JSC * 0.0604 * 0.0398))
#define C_A2       ((float)(JSC * 0.0403 * 0.0306))

#define STEP       0.99984f
#define NITER      3

__device__ __forceinline__ float ex2f(float z) {
    float r;
    asm("ex2.approx.f32 %0, %1;" : "=f"(r) : "f"(z));
    return r;
}

__device__ __forceinline__ void fp_step(float& I, float v_cell, float c0,
                                        float i0, float k) {
    float u = fmaf(I, RS, v_cell);
    float e = ex2f(u * k);
    float t = fmaf(-i0, e, c0);
    t = fmaf(-INV_RSH, u, t);
    I = fmaf(STEP, t - I, I);
}

__global__ void __launch_bounds__(TPB)
segment_physics_kernel(const float* __restrict__ x,
                       const float* __restrict__ f_xn,
                       const float* __restrict__ f_yn,
                       const float* __restrict__ f_xp,
                       const float* __restrict__ f_yp,
                       float* __restrict__ out, int n) {
    __shared__ float s[TPB * NFEAT];

    // Hoisted scalar broadcasts — overlap with the x loads below.
    float v_xn = f_xn[0], v_yn = f_yn[0], v_xp = f_xp[0], v_yp = f_yp[0];

    int lane = threadIdx.x & 31;
    int warp = threadIdx.x >> 5;
    int i = blockIdx.x * TPB + threadIdx.x;

    // Warp w's 32 samples start at global sample (blk*256 + 32w):
    // 88 float4s, loaded by this warp's own lanes only.
    int warp_sample0 = blockIdx.x * TPB + warp * 32;
    bool warp_full = warp_sample0 + 32 <= n;

    float* sw = s + warp * (32 * NFEAT);

    if (warp_full) {
        const float4* src = reinterpret_cast<const float4*>(x) +
                            (size_t)warp_sample0 * NFEAT / 4;
        float4* dst = reinterpret_cast<float4*>(sw);
        float4 a = src[lane];
        float4 b = src[lane + 32];
        float4 c;
        if (lane < WARP_F4 - 64) c = src[lane + 64];
        dst[lane]      = a;
        dst[lane + 32] = b;
        if (lane < WARP_F4 - 64) dst[lane + 64] = c;
    } else {
        // Tail warp: scalar guarded loads.
        int base = warp_sample0 * NFEAT;
        int total = n * NFEAT;
        for (int j = lane; j < 32 * NFEAT; j += 32) {
            int g = base + j;
            if (g < total) sw[j] = x[g];
        }
    }
    __syncwarp();

    if (i >= n) return;

    const float* p = sw + lane * NFEAT;
    float sx   = p[0];
    float sy   = p[1];
    float tpx  = p[2];
    float tnx  = p[3];
    float tpy  = p[4];
    float tny  = p[5];
    float V    = p[6];
    float dist = p[7];

    float r   = SUN_DIST / dist;
    float irr = SOLAR_C * r * r;

    // Dark-side panel's root is negative -> clamps to 0; keep only lit side.
    bool  xp = sx > 0.0f;
    float Gx = irr * fabsf(sx);
    float Tx = xp ? tpx : tnx;
    float fx = xp ? v_xp : v_xn;

    bool  yp = sy > 0.0f;
    float Gy = irr * fabsf(sy);
    float Ty = yp ? tpy : tny;
    float fy = yp ? v_yp : v_yn;
    float cAY  = yp ? C_A2 : C_A1;     // y_pos: small cells, y_neg: large
    float parY = yp ? 10.0f : 6.0f;    // 180/18 vs 108/18

    float v_cell  = V * (1.0f / 18.0f);
    float inv_em1 = ex2f(INV_EM1_ARG);

    float gtx = (Gx * INV_GREF) * fmaf(ALPHA_ISC, Tx - T_REFC, 1.0f);
    float gty = (Gy * INV_GREF) * fmaf(ALPHA_ISC, Ty - T_REFC, 1.0f);

    float kx = (float)LOG2E / (NKB * Tx);
    float ky = (float)LOG2E / (NKB * Ty);

    float iph1 = C_A1 * gtx;           // X large cells  (parallel = 2)
    float iph2 = C_A2 * gtx;           // X small cells  (parallel = 7)
    float iph3 = cAY  * gty;           // Y selected config

    float i0_1 = C_A1 * inv_em1;
    float i0_2 = C_A2 * inv_em1;
    float i0_3 = cAY  * inv_em1;

    float c0_1 = iph1 + i0_1;
    float c0_2 = iph2 + i0_2;
    float c0_3 = iph3 + i0_3;

    float I1 = iph1, I2 = iph2, I3 = iph3;

    #pragma unroll
    for (int it = 0; it < NITER; ++it) {
        fp_step(I1, v_cell, c0_1, i0_1, kx);
        fp_step(I2, v_cell, c0_2, i0_2, kx);
        fp_step(I3, v_cell, c0_3, i0_3, ky);
    }

    float ix = fx * fmaf(2.0f, fmaxf(I1, 0.0f), 7.0f * fmaxf(I2, 0.0f));
    float iy = fy * parY * fmaxf(I3, 0.0f);
    out[i] = 0.92f * (ix + iy);
}

extern "C" void kernel_launch(void* const* d_in, const int* in_sizes, int n_in,
                              void* d_out, int out_size) {
    const float* x    = (const float*)d_in[0];
    const float* f_xn = (const float*)d_in[1];
    const float* f_yn = (const float*)d_in[2];
    const float* f_xp = (const float*)d_in[3];
    const float* f_yp = (const float*)d_in[4];
    float* out = (float*)d_out;

    int n = in_sizes[0] / NFEAT;
    int blocks = (n + TPB - 1) / TPB;
    segment_physics_kernel<<<blocks, TPB>>>(x, f_xn, f_yn, f_xp, f_yp, out, n);
}